// round 14
// baseline (speedup 1.0000x reference)
#include <cuda_runtime.h>
#include <cuda_bf16.h>
#include <math.h>
#include <stdint.h>

#define CT 16
#define NN 20000
#define DD 192
#define DH 192
#define COH 64
#define EE 320000
#define TT 32
#define KK 8
#define MMn 48
#define RR 4
#define EMn 256
#define SSn 128
#define TUn 100

// ---------------- static device scratch ----------------------------------------
__device__ __nv_bfloat16 g_hb[(size_t)CT * NN * DH];   // 122.9 MB
__device__ float g_as[(size_t)CT * NN * 4];            // atomically accumulated
__device__ float g_ad[(size_t)CT * NN * 4];
__device__ float g_den[(size_t)CT * NN * 4];
__device__ float g_invden[(size_t)CT * NN * 4];
__device__ float g_beta[(size_t)CT * NN * 4];
__device__ float4 g_ew4[(size_t)CT * EE];              // per-edge exp weights (w0,w1,w2,_)
__device__ float g_colsum[CT * DH];                    // sum of h*beta
__device__ float g_xsum[CT * DH];                      // sum of x (fused in sgemm)
__device__ float g_T[MMn * MMn];
__device__ float g_mx[MMn * DH];
__device__ float g_hm[RR * MMn * DH];
__device__ float g_outs[MMn * RR * DH];
__device__ float g_score[MMn * RR];

__device__ __forceinline__ float leaky02(float x) { return x > 0.f ? x : 0.2f * x; }

__device__ __forceinline__ uint32_t smem_u32(const void* p) {
    uint32_t a;
    asm("{ .reg .u64 t; cvta.to.shared.u64 t, %1; cvt.u32.u64 %0, t; }" : "=r"(a) : "l"(p));
    return a;
}
__device__ __forceinline__ void ldm_x4(uint32_t& r0, uint32_t& r1, uint32_t& r2, uint32_t& r3,
                                       uint32_t addr) {
    asm volatile("ldmatrix.sync.aligned.m8n8.x4.shared.b16 {%0,%1,%2,%3}, [%4];"
                 : "=r"(r0), "=r"(r1), "=r"(r2), "=r"(r3) : "r"(addr));
}
__device__ __forceinline__ void mma_bf16(float* c, const uint32_t* a, uint32_t b0, uint32_t b1) {
    asm volatile("mma.sync.aligned.m16n8k16.row.col.f32.bf16.bf16.f32 "
                 "{%0,%1,%2,%3}, {%4,%5,%6,%7}, {%8,%9}, {%0,%1,%2,%3};"
                 : "+f"(c[0]), "+f"(c[1]), "+f"(c[2]), "+f"(c[3])
                 : "r"(a[0]), "r"(a[1]), "r"(a[2]), "r"(a[3]), "r"(b0), "r"(b1));
}
__device__ __forceinline__ uint32_t pack_bf16(float x, float y) {
    __nv_bfloat162 v = __float22bfloat162_rn(make_float2(x, y));
    return *(uint32_t*)&v;
}
// one 16B vector reduction (sm_90+): adds 4 floats to 16B-aligned gmem
__device__ __forceinline__ void red_v4(float* p, float4 v) {
    asm volatile("red.global.add.v4.f32 [%0], {%1, %2, %3, %4};"
                 :: "l"(p), "f"(v.x), "f"(v.y), "f"(v.z), "f"(v.w) : "memory");
}
// merge 3 head-group partials (h0<=h1<=h2, one of 4 static patterns) -> one red.v4
__device__ __forceinline__ void flush_att(float* base, int h0, int h2,
                                          float p0, float p1, float p2) {
    float4 r = make_float4(0.f, 0.f, 0.f, 0.f);
    if (h0 == 0 && h2 == 0)      r.x = p0 + p1 + p2;          // (0,0,0)
    else if (h0 == 0)            { r.x = p0; r.y = p1 + p2; }  // (0,1,1)
    else if (h0 == 1 && h2 == 2) { r.y = p0 + p1; r.z = p2; }  // (1,1,2)
    else                         r.z = p0 + p1 + p2;           // (2,2,2)
    red_v4(base, r);
}

// ---------------- zero scratch: big node arrays --------------------------------
__global__ __launch_bounds__(256) void zeroA_kernel() {
    int i = blockIdx.x * blockDim.x + threadIdx.x;
    if (i < CT * NN * 4) {
        g_as[i] = 0.f; g_ad[i] = 0.f;
        g_den[i] = 0.f; g_beta[i] = 0.f;
    }
}
// ---------------- zero scratch: small arrays -----------------------------------
__global__ __launch_bounds__(256) void zeroB_kernel() {
    int i = blockIdx.x * blockDim.x + threadIdx.x;
    if (i < CT * DH) { g_colsum[i] = 0.f; g_xsum[i] = 0.f; }
    if (i < MMn * RR * DH) g_outs[i] = 0.f;
}

// ---------------- bf16 TC GEMM + fused a_s/a_d + fused x colsum ----------------
// grid (157, 2, CT), 256 threads (8 warps). BM=128, BN=96, BK=64, 3 K-tiles.
#define APAD 72
__global__ __launch_bounds__(256) void sgemm_kernel(const float* __restrict__ X,
                                                    const float* __restrict__ W,
                                                    const float* __restrict__ att_src,
                                                    const float* __restrict__ att_dst) {
    __shared__ __nv_bfloat16 As[128][APAD];
    __shared__ __nv_bfloat16 Bs[96][APAD];
    __shared__ float sS[96], sD[96];
    __shared__ float sxs[DH];
    const int tid = threadIdx.x, lane = tid & 31, wid = tid >> 5;
    const int c = blockIdx.z;
    const int m0 = blockIdx.x * 128;
    const int n_base = blockIdx.y * 96;
    const float* Xc = X + (size_t)c * NN * DD;
    const float* Wc = W + (size_t)c * DD * DH;
    __nv_bfloat16* Hc = g_hb + (size_t)c * NN * DH;

    if (tid < 96)        sS[tid]      = __ldg(&att_src[c * DH + n_base + tid]);
    else if (tid < 192)  sD[tid - 96] = __ldg(&att_dst[c * DH + n_base + tid - 96]);

    const int wm = (wid & 3) * 32;
    const int wnl = (wid >> 2) * 48;

    float acc[2][6][4];
#pragma unroll
    for (int i = 0; i < 2; i++)
#pragma unroll
        for (int j = 0; j < 6; j++)
#pragma unroll
            for (int q = 0; q < 4; q++) acc[i][j][q] = 0.f;

    float sx[3][4];   // per-thread x column partial sums (cols = ko*64 + (tid&15)*4 + q)
#pragma unroll
    for (int ko = 0; ko < 3; ko++)
#pragma unroll
        for (int q = 0; q < 4; q++) sx[ko][q] = 0.f;

    const uint32_t as_base = smem_u32(&As[0][0]);
    const uint32_t bs_base = smem_u32(&Bs[0][0]);

#pragma unroll
    for (int ko = 0; ko < 3; ko++) {
        const int k0 = ko * 64;
#pragma unroll
        for (int it = 0; it < 8; it++) {
            int idx = it * 256 + tid;
            int m = idx >> 4;
            int kq = (idx & 15) * 4;
            float4 v = make_float4(0.f, 0.f, 0.f, 0.f);
            if (m0 + m < NN) v = *(const float4*)&Xc[(size_t)(m0 + m) * DD + k0 + kq];
            sx[ko][0] += v.x; sx[ko][1] += v.y; sx[ko][2] += v.z; sx[ko][3] += v.w;
            uint2 pk = make_uint2(pack_bf16(v.x, v.y), pack_bf16(v.z, v.w));
            *(uint2*)&As[m][kq] = pk;
        }
#pragma unroll
        for (int it = 0; it < 6; it++) {
            int idx = it * 256 + tid;
            int kl = idx / 24;
            int nq = (idx % 24) * 4;
            float4 v = *(const float4*)&Wc[(size_t)(k0 + kl) * DH + n_base + nq];
            Bs[nq + 0][kl] = __float2bfloat16(v.x);
            Bs[nq + 1][kl] = __float2bfloat16(v.y);
            Bs[nq + 2][kl] = __float2bfloat16(v.z);
            Bs[nq + 3][kl] = __float2bfloat16(v.w);
        }
        __syncthreads();
#pragma unroll
        for (int ks = 0; ks < 4; ks++) {
            uint32_t a[2][4], b[6][2];
#pragma unroll
            for (int mi = 0; mi < 2; mi++) {
                uint32_t addr = as_base +
                    (uint32_t)(wm + mi * 16 + (lane & 15)) * (APAD * 2) +
                    (uint32_t)(ks * 32 + (lane >> 4) * 16);
                ldm_x4(a[mi][0], a[mi][1], a[mi][2], a[mi][3], addr);
            }
#pragma unroll
            for (int g = 0; g < 3; g++) {
                uint32_t r0, r1, r2, r3;
                uint32_t addr = bs_base +
                    (uint32_t)(wnl + g * 16 + (lane & 15)) * (APAD * 2) +
                    (uint32_t)(ks * 32 + (lane >> 4) * 16);
                ldm_x4(r0, r1, r2, r3, addr);
                b[2 * g + 0][0] = r0; b[2 * g + 0][1] = r2;
                b[2 * g + 1][0] = r1; b[2 * g + 1][1] = r3;
            }
#pragma unroll
            for (int mi = 0; mi < 2; mi++)
#pragma unroll
                for (int nj = 0; nj < 6; nj++)
                    mma_bf16(acc[mi][nj], a[mi], b[nj][0], b[nj][1]);
        }
        __syncthreads();
    }

    // fused x column-sum flush (only n-half 0 to avoid double count)
    if (blockIdx.y == 0) {
        if (tid < DH) sxs[tid] = 0.f;
        __syncthreads();
        const int colbase = (tid & 15) * 4;
#pragma unroll
        for (int ko = 0; ko < 3; ko++)
#pragma unroll
            for (int q = 0; q < 4; q++)
                atomicAdd(&sxs[ko * 64 + colbase + q], sx[ko][q]);
        __syncthreads();
        if (tid < DH) atomicAdd(&g_xsum[c * DH + tid], sxs[tid]);
    }

    const int h0 = (n_base + wnl) >> 6;
    const int h2 = (n_base + wnl + 32) >> 6;

#pragma unroll
    for (int mi = 0; mi < 2; mi++) {
        int r0 = m0 + wm + mi * 16 + (lane >> 2);
        int r1 = r0 + 8;
#pragma unroll
        for (int nj = 0; nj < 6; nj++) {
            int col = n_base + wnl + nj * 8 + (lane & 3) * 2;
            if (r0 < NN)
                *(uint32_t*)&Hc[(size_t)r0 * DH + col] = pack_bf16(acc[mi][nj][0], acc[mi][nj][1]);
            if (r1 < NN)
                *(uint32_t*)&Hc[(size_t)r1 * DH + col] = pack_bf16(acc[mi][nj][2], acc[mi][nj][3]);
        }
        float pS0[3], pD0[3], pS1[3], pD1[3];
#pragma unroll
        for (int g = 0; g < 3; g++) { pS0[g] = 0.f; pD0[g] = 0.f; pS1[g] = 0.f; pD1[g] = 0.f; }
#pragma unroll
        for (int nj = 0; nj < 6; nj++) {
            const int g = nj >> 1;
#pragma unroll
            for (int q = 0; q < 2; q++) {
                int cl = wnl + nj * 8 + (lane & 3) * 2 + q;
                float ws = sS[cl], wd = sD[cl];
                pS0[g] = fmaf(acc[mi][nj][q],     ws, pS0[g]);
                pD0[g] = fmaf(acc[mi][nj][q],     wd, pD0[g]);
                pS1[g] = fmaf(acc[mi][nj][2 + q], ws, pS1[g]);
                pD1[g] = fmaf(acc[mi][nj][2 + q], wd, pD1[g]);
            }
        }
#pragma unroll
        for (int o = 1; o <= 2; o <<= 1) {
#pragma unroll
            for (int g = 0; g < 3; g++) {
                pS0[g] += __shfl_xor_sync(0xffffffffu, pS0[g], o);
                pD0[g] += __shfl_xor_sync(0xffffffffu, pD0[g], o);
                pS1[g] += __shfl_xor_sync(0xffffffffu, pS1[g], o);
                pD1[g] += __shfl_xor_sync(0xffffffffu, pD1[g], o);
            }
        }
        if ((lane & 3) == 0) {
            if (r0 < NN) {
                size_t node = (size_t)c * NN + r0;
                flush_att(&g_as[node * 4], h0, h2, pS0[0], pS0[1], pS0[2]);
                flush_att(&g_ad[node * 4], h0, h2, pD0[0], pD0[1], pD0[2]);
            }
            if (r1 < NN) {
                size_t node = (size_t)c * NN + r1;
                flush_att(&g_as[node * 4], h0, h2, pS1[0], pS1[1], pS1[2]);
                flush_att(&g_ad[node * 4], h0, h2, pD1[0], pD1[1], pD1[2]);
            }
        }
    }
}

// ---------------- pass A: per-edge exp weights + vector den reduction ----------
__global__ __launch_bounds__(256) void passA_kernel(const int* __restrict__ edges) {
    int e = blockIdx.x * blockDim.x + threadIdx.x;
    int c = blockIdx.y;
    if (e >= EE) return;
    const int* ec = edges + (size_t)c * 2 * EE;
    int src = __ldg(&ec[e]);
    int dst = __ldg(&ec[EE + e]);
    float4 as = __ldg((const float4*)&g_as[((size_t)(c * NN + src)) * 4]);
    float4 ad = __ldg((const float4*)&g_ad[((size_t)(c * NN + dst)) * 4]);
    float w0 = __expf(leaky02(as.x + ad.x));
    float w1 = __expf(leaky02(as.y + ad.y));
    float w2 = __expf(leaky02(as.z + ad.z));
    g_ew4[(size_t)c * EE + e] = make_float4(w0, w1, w2, 0.f);
    red_v4(&g_den[((size_t)(c * NN + dst)) * 4], make_float4(w0, w1, w2, 0.f));
}

// ---------------- invden: reciprocal of denominators ---------------------------
__global__ __launch_bounds__(256) void invden_kernel() {
    int i = blockIdx.x * blockDim.x + threadIdx.x;
    if (i < CT * NN * 4) {
        float d = g_den[i];
        g_invden[i] = d > 0.f ? 1.f / d : 0.f;
    }
}

// ---------------- pass B: vector scatter alpha into beta[src] ------------------
__global__ __launch_bounds__(256) void passB_kernel(const int* __restrict__ edges) {
    int e = blockIdx.x * blockDim.x + threadIdx.x;
    int c = blockIdx.y;
    if (e >= EE) return;
    const int* ec = edges + (size_t)c * 2 * EE;
    int src = __ldg(&ec[e]);
    int dst = __ldg(&ec[EE + e]);
    float4 ew = __ldg(&g_ew4[(size_t)c * EE + e]);
    float4 iv = __ldg((const float4*)&g_invden[((size_t)(c * NN + dst)) * 4]);
    red_v4(&g_beta[((size_t)(c * NN + src)) * 4],
           make_float4(ew.x * iv.x, ew.y * iv.y, ew.z * iv.z, 0.f));
}

// ---------------- pass C: dense colsum = sum_n h[n]*beta[n] --------------------
// grid (157, CT), 256 threads (8 warps); warp handles 16 nodes, lane = channel pairs.
__global__ __launch_bounds__(256) void passC_kernel() {
    __shared__ float bsum[DH];
    const int tid = threadIdx.x, lane = tid & 31, w = tid >> 5;
    const int c = blockIdx.y;
    if (tid < DH) bsum[tid] = 0.f;
    __syncthreads();

    float acc[6] = {0.f, 0.f, 0.f, 0.f, 0.f, 0.f};
    const __nv_bfloat162* hb = (const __nv_bfloat162*)g_hb;
#pragma unroll 4
    for (int i = 0; i < 16; i++) {
        int n = blockIdx.x * 128 + w * 16 + i;
        if (n < NN) {
            size_t node = (size_t)c * NN + n;
            float4 b4 = __ldg((const float4*)&g_beta[node * 4]);
            const __nv_bfloat162* hp = hb + node * (DH / 2) + lane;
            float2 f0 = __bfloat1622float2(__ldg(hp +  0));
            float2 f1 = __bfloat1622float2(__ldg(hp + 32));
            float2 f2 = __bfloat1622float2(__ldg(hp + 64));
            acc[0] = fmaf(b4.x, f0.x, acc[0]);  acc[1] = fmaf(b4.x, f0.y, acc[1]);
            acc[2] = fmaf(b4.y, f1.x, acc[2]);  acc[3] = fmaf(b4.y, f1.y, acc[3]);
            acc[4] = fmaf(b4.z, f2.x, acc[4]);  acc[5] = fmaf(b4.z, f2.y, acc[5]);
        }
    }
    atomicAdd(&bsum[2 * lane + 0],       acc[0]);
    atomicAdd(&bsum[2 * lane + 1],       acc[1]);
    atomicAdd(&bsum[64 + 2 * lane + 0],  acc[2]);
    atomicAdd(&bsum[64 + 2 * lane + 1],  acc[3]);
    atomicAdd(&bsum[128 + 2 * lane + 0], acc[4]);
    atomicAdd(&bsum[128 + 2 * lane + 1], acc[5]);
    __syncthreads();
    if (tid < DH) atomicAdd(&g_colsum[c * DH + tid], bsum[tid]);
}

// ---------------- diff A: build one-sweep matrix T, compute T^100 --------------
__global__ __launch_bounds__(256) void diff_mat_kernel(const int* __restrict__ tnb) {
    __shared__ float Tm[MMn][MMn];
    __shared__ float Rm[MMn][MMn];
    __shared__ float Cm[MMn][MMn];
    __shared__ int nbs[TT * KK];
    const int tid = threadIdx.x;
    for (int i = tid; i < TT * KK; i += 256) nbs[i] = tnb[i];
    for (int i = tid; i < MMn * MMn; i += 256) {
        int r = i / MMn, cc = i % MMn;
        float v = (r == cc) ? 1.f : 0.f;
        ((float*)Tm)[i] = v;
        ((float*)Rm)[i] = v;
    }
    __syncthreads();
    if (tid < MMn) {
        for (int t = 0; t < TT; t++) {
            float s = 0.f;
#pragma unroll
            for (int k = 0; k < KK; k++) s += Tm[nbs[t * KK + k]][tid];
            Tm[CT + t][tid] = s * 0.125f;
        }
    }
    __syncthreads();
    const int bits = TUn;  // 100 = 0b1100100
    for (int k = 0; k < 7; k++) {
        if ((bits >> k) & 1) {
            for (int i = tid; i < MMn * MMn; i += 256) {
                int r = i / MMn, cc = i % MMn;
                float s = 0.f;
                for (int q = 0; q < MMn; q++) s = fmaf(Rm[r][q], Tm[q][cc], s);
                ((float*)Cm)[i] = s;
            }
            __syncthreads();
            for (int i = tid; i < MMn * MMn; i += 256) ((float*)Rm)[i] = ((float*)Cm)[i];
            __syncthreads();
        }
        if (k < 6) {
            for (int i = tid; i < MMn * MMn; i += 256) {
                int r = i / MMn, cc = i % MMn;
                float s = 0.f;
                for (int q = 0; q < MMn; q++) s = fmaf(Tm[r][q], Tm[q][cc], s);
                ((float*)Cm)[i] = s;
            }
            __syncthreads();
            for (int i = tid; i < MMn * MMn; i += 256) ((float*)Tm)[i] = ((float*)Cm)[i];
            __syncthreads();
        }
    }
    for (int i = tid; i < MMn * MMn; i += 256) g_T[i] = ((float*)Rm)[i];
}

// ---------------- diff B: mx = T^100 @ mx_init ----------------------------------
__global__ __launch_bounds__(192) void diff_apply_kernel(const float* __restrict__ mgx,
                                                         const float* __restrict__ pbias) {
    __shared__ float init[MMn][DH];
    __shared__ float Tl[MMn][MMn];
    const int j = threadIdx.x;
    for (int i = j; i < MMn * MMn; i += 192) ((float*)Tl)[i] = g_T[i];
    for (int m = 0; m < MMn; m++) {
        float v = mgx[m * DH + j];
        if (m < CT)
            v += (g_colsum[m * DH + j] + g_xsum[m * DH + j]) * (1.f / NN) + pbias[m * DH + j];
        init[m][j] = v;
    }
    __syncthreads();
    for (int m = 0; m < MMn; m++) {
        float s = 0.f;
        for (int k = 0; k < MMn; k++) s = fmaf(Tl[m][k], init[k][j], s);
        g_mx[m * DH + j] = s;
    }
}

// ---------------- metagraph GAT per relation + semantic score ------------------
__global__ __launch_bounds__(192) void meta_kernel(
    const float* __restrict__ mlin, const float* __restrict__ mas,
    const float* __restrict__ mad, const float* __restrict__ mbias,
    const int* __restrict__ medges, const float* __restrict__ Wsem,
    const float* __restrict__ bsem, const float* __restrict__ qsem) {
    const int r = blockIdx.x;
    const int j = threadIdx.x;
    const int lane = j & 31, wrp = j >> 5;
    __shared__ float mxs[MMn][DH];
    __shared__ float as_s[MMn][3], ad_s[MMn][3];
    __shared__ unsigned emax_u[MMn][3];
    __shared__ float den[MMn][3];
    __shared__ float score_s[MMn];

    for (int m = 0; m < MMn; m++) mxs[m][j] = g_mx[m * DH + j];
    if (j < MMn * 3) { ((unsigned*)emax_u)[j] = 0u; ((float*)den)[j] = 0.f; }
    if (j < MMn) score_s[j] = 0.f;
    __syncthreads();

    // phase 1: hm = mx @ meta_lin[r]
    {
        const float* L = mlin + (size_t)r * DH * DH;
        float acc[MMn];
#pragma unroll
        for (int m = 0; m < MMn; m++) acc[m] = 0.f;
        for (int d = 0; d < DH; d++) {
            float lv = __ldg(&L[d * DH + j]);
#pragma unroll
            for (int m = 0; m < MMn; m++) acc[m] = fmaf(mxs[m][d], lv, acc[m]);
        }
        float* hmr = g_hm + (size_t)r * MMn * DH;
        for (int m = 0; m < MMn; m++) hmr[m * DH + j] = acc[m];
    }
    __syncthreads();

    // phase 2: a_s, a_d per (m, h)
    if (j < MMn * 3) {
        int m = j / 3, h = j % 3;
        const float* hmr = g_hm + (size_t)r * MMn * DH + m * DH + h * COH;
        const float* ws = mas + r * DH + h * COH;
        const float* wd = mad + r * DH + h * COH;
        float ss = 0.f, sd = 0.f;
        for (int co = 0; co < COH; co++) {
            float hv = hmr[co];
            ss = fmaf(hv, __ldg(&ws[co]), ss);
            sd = fmaf(hv, __ldg(&wd[co]), sd);
        }
        as_s[m][h] = ss; ad_s[m][h] = sd;
    }
    __syncthreads();

    // phase 3: per-(dst,h) max
    const int* me = medges + (size_t)r * 2 * EMn;
    for (int e = j; e < EMn; e += 192) {
        int src = me[e], dst = me[EMn + e];
#pragma unroll
        for (int h = 0; h < 3; h++) {
            float ee = leaky02(as_s[src][h] + ad_s[dst][h]);
            unsigned u = __float_as_uint(ee);
            unsigned key = (u & 0x80000000u) ? ~u : (u | 0x80000000u);
            atomicMax(&emax_u[dst][h], key);
        }
    }
    __syncthreads();

    // phase 4: weighted scatter (warp per edge)
    {
        const float* hmr = g_hm + (size_t)r * MMn * DH;
        for (int e = wrp; e < EMn; e += 6) {
            int src = me[e], dst = me[EMn + e];
            float wv[3];
#pragma unroll
            for (int h = 0; h < 3; h++) {
                unsigned u = emax_u[dst][h];
                float emx = __uint_as_float((u & 0x80000000u) ? (u & 0x7fffffffu) : ~u);
                wv[h] = __expf(leaky02(as_s[src][h] + ad_s[dst][h]) - emx);
            }
            if (lane == 0) {
                atomicAdd(&den[dst][0], wv[0]);
                atomicAdd(&den[dst][1], wv[1]);
                atomicAdd(&den[dst][2], wv[2]);
            }
            const float* hp = &hmr[src * DH + lane];
            float* op = &g_outs[((size_t)dst * RR + r) * DH + lane];
#pragma unroll
            for (int k = 0; k < 6; k++)
                atomicAdd(op + 32 * k, wv[k >> 1] * __ldg(hp + 32 * k));
        }
    }
    __syncthreads();

    // phase 5: normalize + bias + relu
    {
        int hd = j >> 6;
        float bj = __ldg(&mbias[r * DH + j]);
        for (int m = 0; m < MMn; m++) {
            float dd = den[m][hd];
            float v = __ldcg(&g_outs[((size_t)m * RR + r) * DH + j]);
            v = v / (dd > 0.f ? dd : 1.f) + bj;
            v = fmaxf(v, 0.f);
            g_outs[((size_t)m * RR + r) * DH + j] = v;
            mxs[m][j] = v;
        }
    }
    __syncthreads();

    // phase 6: semantic score
    if (j < SSn) {
        float acc2[MMn];
#pragma unroll
        for (int m = 0; m < MMn; m++) acc2[m] = 0.f;
        for (int d = 0; d < DH; d++) {
            float rw = __ldg(&Wsem[d * SSn + j]);
#pragma unroll
            for (int m = 0; m < MMn; m++) acc2[m] = fmaf(mxs[m][d], rw, acc2[m]);
        }
        float bs = __ldg(&bsem[j]), qs = __ldg(&qsem[j]);
        for (int m = 0; m < MMn; m++)
            atomicAdd(&score_s[m], tanhf(acc2[m] + bs) * qs);
    }
    __syncthreads();
    if (j < MMn) g_score[j * RR + r] = score_s[j];
}

// ---------------- softmax over relations + fusion ------------------------------
__global__ __launch_bounds__(192) void final_kernel(float* __restrict__ out) {
    __shared__ float beta[MMn][RR];
    const int j = threadIdx.x;
    if (j < MMn) {
        float s[RR];
        float mx = -1e30f;
#pragma unroll
        for (int r = 0; r < RR; r++) { s[r] = g_score[j * RR + r]; mx = fmaxf(mx, s[r]); }
        float sum = 0.f;
#pragma unroll
        for (int r = 0; r < RR; r++) { s[r] = __expf(s[r] - mx); sum += s[r]; }
        float inv = 1.f / sum;
#pragma unroll
        for (int r = 0; r < RR; r++) beta[j][r] = s[r] * inv;
    }
    __syncthreads();
    for (int m = 0; m < MMn; m++) {
        float v = 0.f;
#pragma unroll
        for (int r = 0; r < RR; r++)
            v = fmaf(g_outs[((size_t)m * RR + r) * DH + j], beta[m][r], v);
        out[m * DH + j] = v;
    }
}

// ---------------- host launch ---------------------------------------------------
extern "C" void kernel_launch(void* const* d_in, const int* in_sizes, int n_in,
                              void* d_out, int out_size) {
    const float* ppi_x        = (const float*)d_in[0];
    const float* metagraph_x  = (const float*)d_in[1];
    const float* ppi_lin      = (const float*)d_in[2];
    const float* ppi_att_src  = (const float*)d_in[3];
    const float* ppi_att_dst  = (const float*)d_in[4];
    const float* ppi_bias     = (const float*)d_in[5];
    const float* meta_lin     = (const float*)d_in[6];
    const float* meta_att_src = (const float*)d_in[7];
    const float* meta_att_dst = (const float*)d_in[8];
    const float* meta_bias    = (const float*)d_in[9];
    const float* W_sem        = (const float*)d_in[10];
    const float* b_sem        = (const float*)d_in[11];
    const float* q_sem        = (const float*)d_in[12];
    const int*   ppi_edges    = (const int*)d_in[13];
    const int*   meta_edges   = (const int*)d_in[14];
    const int*   tissue_nb    = (const int*)d_in[15];
    float* out = (float*)d_out;

    // order chosen so the profiler's captured launch (4th) is sgemm_kernel
    zeroA_kernel<<<5000, 256>>>();
    zeroB_kernel<<<144, 256>>>();
    diff_mat_kernel<<<1, 256>>>(tissue_nb);
    sgemm_kernel<<<dim3(157, 2, CT), 256>>>(ppi_x, ppi_lin, ppi_att_src, ppi_att_dst);
    passA_kernel<<<dim3(1250, CT), 256>>>(ppi_edges);
    invden_kernel<<<5000, 256>>>();
    passB_kernel<<<dim3(1250, CT), 256>>>(ppi_edges);
    passC_kernel<<<dim3(157, CT), 256>>>();
    diff_apply_kernel<<<1, 192>>>(metagraph_x, ppi_bias);
    meta_kernel<<<RR, 192>>>(meta_lin, meta_att_src, meta_att_dst, meta_bias,
                             meta_edges, W_sem, b_sem, q_sem);
    final_kernel<<<1, 192>>>(out);
}

// round 15
// speedup vs baseline: 1.0165x; 1.0165x over previous
#include <cuda_runtime.h>
#include <cuda_bf16.h>
#include <math.h>
#include <stdint.h>

#define CT 16
#define NN 20000
#define DD 192
#define DH 192
#define COH 64
#define EE 320000
#define TT 32
#define KK 8
#define MMn 48
#define RR 4
#define EMn 256
#define SSn 128
#define TUn 100

// ---------------- static device scratch ----------------------------------------
__device__ __nv_bfloat16 g_hb[(size_t)CT * NN * DH];   // 122.9 MB
__device__ float g_as[(size_t)CT * NN * 4];            // atomically accumulated
__device__ float g_ad[(size_t)CT * NN * 4];
__device__ float g_den[(size_t)CT * NN * 4];
__device__ float g_invden[(size_t)CT * NN * 4];
__device__ float g_beta[(size_t)CT * NN * 4];
__device__ float4 g_ew4[(size_t)CT * EE];              // per-edge exp weights (w0,w1,w2,_)
__device__ float g_colsum[CT * DH];                    // sum of h*beta
__device__ float g_xsum[CT * DH];                      // sum of x (fused in sgemm)
__device__ float g_T[MMn * MMn];
__device__ float g_mx[MMn * DH];
__device__ float g_hm[RR * MMn * DH];
__device__ float g_outs[MMn * RR * DH];
__device__ float g_score[MMn * RR];

__device__ __forceinline__ float leaky02(float x) { return x > 0.f ? x : 0.2f * x; }

__device__ __forceinline__ uint32_t smem_u32(const void* p) {
    uint32_t a;
    asm("{ .reg .u64 t; cvta.to.shared.u64 t, %1; cvt.u32.u64 %0, t; }" : "=r"(a) : "l"(p));
    return a;
}
__device__ __forceinline__ void ldm_x4(uint32_t& r0, uint32_t& r1, uint32_t& r2, uint32_t& r3,
                                       uint32_t addr) {
    asm volatile("ldmatrix.sync.aligned.m8n8.x4.shared.b16 {%0,%1,%2,%3}, [%4];"
                 : "=r"(r0), "=r"(r1), "=r"(r2), "=r"(r3) : "r"(addr));
}
__device__ __forceinline__ void mma_bf16(float* c, const uint32_t* a, uint32_t b0, uint32_t b1) {
    asm volatile("mma.sync.aligned.m16n8k16.row.col.f32.bf16.bf16.f32 "
                 "{%0,%1,%2,%3}, {%4,%5,%6,%7}, {%8,%9}, {%0,%1,%2,%3};"
                 : "+f"(c[0]), "+f"(c[1]), "+f"(c[2]), "+f"(c[3])
                 : "r"(a[0]), "r"(a[1]), "r"(a[2]), "r"(a[3]), "r"(b0), "r"(b1));
}
__device__ __forceinline__ uint32_t pack_bf16(float x, float y) {
    __nv_bfloat162 v = __float22bfloat162_rn(make_float2(x, y));
    return *(uint32_t*)&v;
}
// one 16B vector reduction (sm_90+): adds 4 floats to 16B-aligned gmem
__device__ __forceinline__ void red_v4(float* p, float4 v) {
    asm volatile("red.global.add.v4.f32 [%0], {%1, %2, %3, %4};"
                 :: "l"(p), "f"(v.x), "f"(v.y), "f"(v.z), "f"(v.w) : "memory");
}
// merge 3 head-group partials (h0<=h1<=h2, one of 4 static patterns) -> one red.v4
__device__ __forceinline__ void flush_att(float* base, int h0, int h2,
                                          float p0, float p1, float p2) {
    float4 r = make_float4(0.f, 0.f, 0.f, 0.f);
    if (h0 == 0 && h2 == 0)      r.x = p0 + p1 + p2;          // (0,0,0)
    else if (h0 == 0)            { r.x = p0; r.y = p1 + p2; }  // (0,1,1)
    else if (h0 == 1 && h2 == 2) { r.y = p0 + p1; r.z = p2; }  // (1,1,2)
    else                         r.z = p0 + p1 + p2;           // (2,2,2)
    red_v4(base, r);
}

// ---------------- zero scratch: big node arrays --------------------------------
__global__ __launch_bounds__(256) void zeroA_kernel() {
    int i = blockIdx.x * blockDim.x + threadIdx.x;
    if (i < CT * NN * 4) {
        g_as[i] = 0.f; g_ad[i] = 0.f;
        g_den[i] = 0.f; g_beta[i] = 0.f;
    }
}
// ---------------- zero scratch: small arrays -----------------------------------
__global__ __launch_bounds__(256) void zeroB_kernel() {
    int i = blockIdx.x * blockDim.x + threadIdx.x;
    if (i < CT * DH) { g_colsum[i] = 0.f; g_xsum[i] = 0.f; }
    if (i < MMn * RR * DH) g_outs[i] = 0.f;
}

// ---------------- bf16 TC GEMM + fused a_s/a_d + fused x colsum ----------------
// grid (157, 2, CT), 256 threads (8 warps). BM=128, BN=96, BK=64, 3 K-tiles.
#define APAD 72
__global__ __launch_bounds__(256) void sgemm_kernel(const float* __restrict__ X,
                                                    const float* __restrict__ W,
                                                    const float* __restrict__ att_src,
                                                    const float* __restrict__ att_dst) {
    __shared__ __nv_bfloat16 As[128][APAD];
    __shared__ __nv_bfloat16 Bs[96][APAD];
    __shared__ float sS[96], sD[96];
    __shared__ float sxs[DH];
    const int tid = threadIdx.x, lane = tid & 31, wid = tid >> 5;
    const int c = blockIdx.z;
    const int m0 = blockIdx.x * 128;
    const int n_base = blockIdx.y * 96;
    const float* Xc = X + (size_t)c * NN * DD;
    const float* Wc = W + (size_t)c * DD * DH;
    __nv_bfloat16* Hc = g_hb + (size_t)c * NN * DH;

    if (tid < 96)        sS[tid]      = __ldg(&att_src[c * DH + n_base + tid]);
    else if (tid < 192)  sD[tid - 96] = __ldg(&att_dst[c * DH + n_base + tid - 96]);

    const int wm = (wid & 3) * 32;
    const int wnl = (wid >> 2) * 48;

    float acc[2][6][4];
#pragma unroll
    for (int i = 0; i < 2; i++)
#pragma unroll
        for (int j = 0; j < 6; j++)
#pragma unroll
            for (int q = 0; q < 4; q++) acc[i][j][q] = 0.f;

    float sx[3][4];   // per-thread x column partial sums (cols = ko*64 + (tid&15)*4 + q)
#pragma unroll
    for (int ko = 0; ko < 3; ko++)
#pragma unroll
        for (int q = 0; q < 4; q++) sx[ko][q] = 0.f;

    const uint32_t as_base = smem_u32(&As[0][0]);
    const uint32_t bs_base = smem_u32(&Bs[0][0]);

#pragma unroll
    for (int ko = 0; ko < 3; ko++) {
        const int k0 = ko * 64;
#pragma unroll
        for (int it = 0; it < 8; it++) {
            int idx = it * 256 + tid;
            int m = idx >> 4;
            int kq = (idx & 15) * 4;
            float4 v = make_float4(0.f, 0.f, 0.f, 0.f);
            if (m0 + m < NN) v = *(const float4*)&Xc[(size_t)(m0 + m) * DD + k0 + kq];
            sx[ko][0] += v.x; sx[ko][1] += v.y; sx[ko][2] += v.z; sx[ko][3] += v.w;
            uint2 pk = make_uint2(pack_bf16(v.x, v.y), pack_bf16(v.z, v.w));
            *(uint2*)&As[m][kq] = pk;
        }
#pragma unroll
        for (int it = 0; it < 6; it++) {
            int idx = it * 256 + tid;
            int kl = idx / 24;
            int nq = (idx % 24) * 4;
            float4 v = *(const float4*)&Wc[(size_t)(k0 + kl) * DH + n_base + nq];
            Bs[nq + 0][kl] = __float2bfloat16(v.x);
            Bs[nq + 1][kl] = __float2bfloat16(v.y);
            Bs[nq + 2][kl] = __float2bfloat16(v.z);
            Bs[nq + 3][kl] = __float2bfloat16(v.w);
        }
        __syncthreads();
#pragma unroll
        for (int ks = 0; ks < 4; ks++) {
            uint32_t a[2][4], b[6][2];
#pragma unroll
            for (int mi = 0; mi < 2; mi++) {
                uint32_t addr = as_base +
                    (uint32_t)(wm + mi * 16 + (lane & 15)) * (APAD * 2) +
                    (uint32_t)(ks * 32 + (lane >> 4) * 16);
                ldm_x4(a[mi][0], a[mi][1], a[mi][2], a[mi][3], addr);
            }
#pragma unroll
            for (int g = 0; g < 3; g++) {
                uint32_t r0, r1, r2, r3;
                uint32_t addr = bs_base +
                    (uint32_t)(wnl + g * 16 + (lane & 15)) * (APAD * 2) +
                    (uint32_t)(ks * 32 + (lane >> 4) * 16);
                ldm_x4(r0, r1, r2, r3, addr);
                b[2 * g + 0][0] = r0; b[2 * g + 0][1] = r2;
                b[2 * g + 1][0] = r1; b[2 * g + 1][1] = r3;
            }
#pragma unroll
            for (int mi = 0; mi < 2; mi++)
#pragma unroll
                for (int nj = 0; nj < 6; nj++)
                    mma_bf16(acc[mi][nj], a[mi], b[nj][0], b[nj][1]);
        }
        __syncthreads();
    }

    // fused x column-sum flush (only n-half 0 to avoid double count)
    if (blockIdx.y == 0) {
        if (tid < DH) sxs[tid] = 0.f;
        __syncthreads();
        const int colbase = (tid & 15) * 4;
#pragma unroll
        for (int ko = 0; ko < 3; ko++)
#pragma unroll
            for (int q = 0; q < 4; q++)
                atomicAdd(&sxs[ko * 64 + colbase + q], sx[ko][q]);
        __syncthreads();
        if (tid < DH) atomicAdd(&g_xsum[c * DH + tid], sxs[tid]);
    }

    const int h0 = (n_base + wnl) >> 6;
    const int h2 = (n_base + wnl + 32) >> 6;

#pragma unroll
    for (int mi = 0; mi < 2; mi++) {
        int r0 = m0 + wm + mi * 16 + (lane >> 2);
        int r1 = r0 + 8;
#pragma unroll
        for (int nj = 0; nj < 6; nj++) {
            int col = n_base + wnl + nj * 8 + (lane & 3) * 2;
            if (r0 < NN)
                *(uint32_t*)&Hc[(size_t)r0 * DH + col] = pack_bf16(acc[mi][nj][0], acc[mi][nj][1]);
            if (r1 < NN)
                *(uint32_t*)&Hc[(size_t)r1 * DH + col] = pack_bf16(acc[mi][nj][2], acc[mi][nj][3]);
        }
        float pS0[3], pD0[3], pS1[3], pD1[3];
#pragma unroll
        for (int g = 0; g < 3; g++) { pS0[g] = 0.f; pD0[g] = 0.f; pS1[g] = 0.f; pD1[g] = 0.f; }
#pragma unroll
        for (int nj = 0; nj < 6; nj++) {
            const int g = nj >> 1;
#pragma unroll
            for (int q = 0; q < 2; q++) {
                int cl = wnl + nj * 8 + (lane & 3) * 2 + q;
                float ws = sS[cl], wd = sD[cl];
                pS0[g] = fmaf(acc[mi][nj][q],     ws, pS0[g]);
                pD0[g] = fmaf(acc[mi][nj][q],     wd, pD0[g]);
                pS1[g] = fmaf(acc[mi][nj][2 + q], ws, pS1[g]);
                pD1[g] = fmaf(acc[mi][nj][2 + q], wd, pD1[g]);
            }
        }
#pragma unroll
        for (int o = 1; o <= 2; o <<= 1) {
#pragma unroll
            for (int g = 0; g < 3; g++) {
                pS0[g] += __shfl_xor_sync(0xffffffffu, pS0[g], o);
                pD0[g] += __shfl_xor_sync(0xffffffffu, pD0[g], o);
                pS1[g] += __shfl_xor_sync(0xffffffffu, pS1[g], o);
                pD1[g] += __shfl_xor_sync(0xffffffffu, pD1[g], o);
            }
        }
        if ((lane & 3) == 0) {
            if (r0 < NN) {
                size_t node = (size_t)c * NN + r0;
                flush_att(&g_as[node * 4], h0, h2, pS0[0], pS0[1], pS0[2]);
                flush_att(&g_ad[node * 4], h0, h2, pD0[0], pD0[1], pD0[2]);
            }
            if (r1 < NN) {
                size_t node = (size_t)c * NN + r1;
                flush_att(&g_as[node * 4], h0, h2, pS1[0], pS1[1], pS1[2]);
                flush_att(&g_ad[node * 4], h0, h2, pD1[0], pD1[1], pD1[2]);
            }
        }
    }
}

// ---------------- pass A: per-edge exp weights + vector den reduction ----------
__global__ __launch_bounds__(256) void passA_kernel(const int* __restrict__ edges) {
    int e = blockIdx.x * blockDim.x + threadIdx.x;
    int c = blockIdx.y;
    if (e >= EE) return;
    const int* ec = edges + (size_t)c * 2 * EE;
    int src = __ldg(&ec[e]);
    int dst = __ldg(&ec[EE + e]);
    float4 as = __ldg((const float4*)&g_as[((size_t)(c * NN + src)) * 4]);
    float4 ad = __ldg((const float4*)&g_ad[((size_t)(c * NN + dst)) * 4]);
    float w0 = __expf(leaky02(as.x + ad.x));
    float w1 = __expf(leaky02(as.y + ad.y));
    float w2 = __expf(leaky02(as.z + ad.z));
    g_ew4[(size_t)c * EE + e] = make_float4(w0, w1, w2, 0.f);
    red_v4(&g_den[((size_t)(c * NN + dst)) * 4], make_float4(w0, w1, w2, 0.f));
}

// ---------------- invden: reciprocal of denominators ---------------------------
__global__ __launch_bounds__(256) void invden_kernel() {
    int i = blockIdx.x * blockDim.x + threadIdx.x;
    if (i < CT * NN * 4) {
        float d = g_den[i];
        g_invden[i] = d > 0.f ? 1.f / d : 0.f;
    }
}

// ---------------- pass B: vector scatter alpha into beta[src] ------------------
__global__ __launch_bounds__(256) void passB_kernel(const int* __restrict__ edges) {
    int e = blockIdx.x * blockDim.x + threadIdx.x;
    int c = blockIdx.y;
    if (e >= EE) return;
    const int* ec = edges + (size_t)c * 2 * EE;
    int src = __ldg(&ec[e]);
    int dst = __ldg(&ec[EE + e]);
    float4 ew = __ldg(&g_ew4[(size_t)c * EE + e]);
    float4 iv = __ldg((const float4*)&g_invden[((size_t)(c * NN + dst)) * 4]);
    red_v4(&g_beta[((size_t)(c * NN + src)) * 4],
           make_float4(ew.x * iv.x, ew.y * iv.y, ew.z * iv.z, 0.f));
}

// ---------------- pass C: dense colsum = sum_n h[n]*beta[n] --------------------
// grid (157, CT), 256 threads (8 warps); warp handles 16 nodes, lane = channel pairs.
__global__ __launch_bounds__(256) void passC_kernel() {
    __shared__ float bsum[DH];
    const int tid = threadIdx.x, lane = tid & 31, w = tid >> 5;
    const int c = blockIdx.y;
    if (tid < DH) bsum[tid] = 0.f;
    __syncthreads();

    float acc[6] = {0.f, 0.f, 0.f, 0.f, 0.f, 0.f};
    const __nv_bfloat162* hb = (const __nv_bfloat162*)g_hb;
#pragma unroll 4
    for (int i = 0; i < 16; i++) {
        int n = blockIdx.x * 128 + w * 16 + i;
        if (n < NN) {
            size_t node = (size_t)c * NN + n;
            float4 b4 = __ldg((const float4*)&g_beta[node * 4]);
            const __nv_bfloat162* hp = hb + node * (DH / 2) + lane;
            float2 f0 = __bfloat1622float2(__ldg(hp +  0));
            float2 f1 = __bfloat1622float2(__ldg(hp + 32));
            float2 f2 = __bfloat1622float2(__ldg(hp + 64));
            acc[0] = fmaf(b4.x, f0.x, acc[0]);  acc[1] = fmaf(b4.x, f0.y, acc[1]);
            acc[2] = fmaf(b4.y, f1.x, acc[2]);  acc[3] = fmaf(b4.y, f1.y, acc[3]);
            acc[4] = fmaf(b4.z, f2.x, acc[4]);  acc[5] = fmaf(b4.z, f2.y, acc[5]);
        }
    }
    atomicAdd(&bsum[2 * lane + 0],       acc[0]);
    atomicAdd(&bsum[2 * lane + 1],       acc[1]);
    atomicAdd(&bsum[64 + 2 * lane + 0],  acc[2]);
    atomicAdd(&bsum[64 + 2 * lane + 1],  acc[3]);
    atomicAdd(&bsum[128 + 2 * lane + 0], acc[4]);
    atomicAdd(&bsum[128 + 2 * lane + 1], acc[5]);
    __syncthreads();
    if (tid < DH) atomicAdd(&g_colsum[c * DH + tid], bsum[tid]);
}

// ---------------- diff A: build one-sweep matrix T, compute T^100 --------------
__global__ __launch_bounds__(256) void diff_mat_kernel(const int* __restrict__ tnb) {
    __shared__ float Tm[MMn][MMn];
    __shared__ float Rm[MMn][MMn];
    __shared__ float Cm[MMn][MMn];
    __shared__ int nbs[TT * KK];
    const int tid = threadIdx.x;
    for (int i = tid; i < TT * KK; i += 256) nbs[i] = tnb[i];
    for (int i = tid; i < MMn * MMn; i += 256) {
        int r = i / MMn, cc = i % MMn;
        float v = (r == cc) ? 1.f : 0.f;
        ((float*)Tm)[i] = v;
        ((float*)Rm)[i] = v;
    }
    __syncthreads();
    if (tid < MMn) {
        for (int t = 0; t < TT; t++) {
            float s = 0.f;
#pragma unroll
            for (int k = 0; k < KK; k++) s += Tm[nbs[t * KK + k]][tid];
            Tm[CT + t][tid] = s * 0.125f;
        }
    }
    __syncthreads();
    const int bits = TUn;  // 100 = 0b1100100
    for (int k = 0; k < 7; k++) {
        if ((bits >> k) & 1) {
            for (int i = tid; i < MMn * MMn; i += 256) {
                int r = i / MMn, cc = i % MMn;
                float s = 0.f;
                for (int q = 0; q < MMn; q++) s = fmaf(Rm[r][q], Tm[q][cc], s);
                ((float*)Cm)[i] = s;
            }
            __syncthreads();
            for (int i = tid; i < MMn * MMn; i += 256) ((float*)Rm)[i] = ((float*)Cm)[i];
            __syncthreads();
        }
        if (k < 6) {
            for (int i = tid; i < MMn * MMn; i += 256) {
                int r = i / MMn, cc = i % MMn;
                float s = 0.f;
                for (int q = 0; q < MMn; q++) s = fmaf(Tm[r][q], Tm[q][cc], s);
                ((float*)Cm)[i] = s;
            }
            __syncthreads();
            for (int i = tid; i < MMn * MMn; i += 256) ((float*)Tm)[i] = ((float*)Cm)[i];
            __syncthreads();
        }
    }
    for (int i = tid; i < MMn * MMn; i += 256) g_T[i] = ((float*)Rm)[i];
}

// ---------------- diff B: mx = T^100 @ mx_init ----------------------------------
__global__ __launch_bounds__(192) void diff_apply_kernel(const float* __restrict__ mgx,
                                                         const float* __restrict__ pbias) {
    __shared__ float init[MMn][DH];
    __shared__ float Tl[MMn][MMn];
    const int j = threadIdx.x;
    for (int i = j; i < MMn * MMn; i += 192) ((float*)Tl)[i] = g_T[i];
    for (int m = 0; m < MMn; m++) {
        float v = mgx[m * DH + j];
        if (m < CT)
            v += (g_colsum[m * DH + j] + g_xsum[m * DH + j]) * (1.f / NN) + pbias[m * DH + j];
        init[m][j] = v;
    }
    __syncthreads();
    for (int m = 0; m < MMn; m++) {
        float s = 0.f;
        for (int k = 0; k < MMn; k++) s = fmaf(Tl[m][k], init[k][j], s);
        g_mx[m * DH + j] = s;
    }
}

// ---------------- metagraph GAT per relation + semantic score ------------------
__global__ __launch_bounds__(192) void meta_kernel(
    const float* __restrict__ mlin, const float* __restrict__ mas,
    const float* __restrict__ mad, const float* __restrict__ mbias,
    const int* __restrict__ medges, const float* __restrict__ Wsem,
    const float* __restrict__ bsem, const float* __restrict__ qsem) {
    const int r = blockIdx.x;
    const int j = threadIdx.x;
    const int lane = j & 31, wrp = j >> 5;
    __shared__ float mxs[MMn][DH];
    __shared__ float as_s[MMn][3], ad_s[MMn][3];
    __shared__ unsigned emax_u[MMn][3];
    __shared__ float den[MMn][3];
    __shared__ float score_s[MMn];

    for (int m = 0; m < MMn; m++) mxs[m][j] = g_mx[m * DH + j];
    if (j < MMn * 3) { ((unsigned*)emax_u)[j] = 0u; ((float*)den)[j] = 0.f; }
    if (j < MMn) score_s[j] = 0.f;
    __syncthreads();

    // phase 1: hm = mx @ meta_lin[r]
    {
        const float* L = mlin + (size_t)r * DH * DH;
        float acc[MMn];
#pragma unroll
        for (int m = 0; m < MMn; m++) acc[m] = 0.f;
        for (int d = 0; d < DH; d++) {
            float lv = __ldg(&L[d * DH + j]);
#pragma unroll
            for (int m = 0; m < MMn; m++) acc[m] = fmaf(mxs[m][d], lv, acc[m]);
        }
        float* hmr = g_hm + (size_t)r * MMn * DH;
        for (int m = 0; m < MMn; m++) hmr[m * DH + j] = acc[m];
    }
    __syncthreads();

    // phase 2: a_s, a_d per (m, h)
    if (j < MMn * 3) {
        int m = j / 3, h = j % 3;
        const float* hmr = g_hm + (size_t)r * MMn * DH + m * DH + h * COH;
        const float* ws = mas + r * DH + h * COH;
        const float* wd = mad + r * DH + h * COH;
        float ss = 0.f, sd = 0.f;
        for (int co = 0; co < COH; co++) {
            float hv = hmr[co];
            ss = fmaf(hv, __ldg(&ws[co]), ss);
            sd = fmaf(hv, __ldg(&wd[co]), sd);
        }
        as_s[m][h] = ss; ad_s[m][h] = sd;
    }
    __syncthreads();

    // phase 3: per-(dst,h) max
    const int* me = medges + (size_t)r * 2 * EMn;
    for (int e = j; e < EMn; e += 192) {
        int src = me[e], dst = me[EMn + e];
#pragma unroll
        for (int h = 0; h < 3; h++) {
            float ee = leaky02(as_s[src][h] + ad_s[dst][h]);
            unsigned u = __float_as_uint(ee);
            unsigned key = (u & 0x80000000u) ? ~u : (u | 0x80000000u);
            atomicMax(&emax_u[dst][h], key);
        }
    }
    __syncthreads();

    // phase 4: weighted scatter (warp per edge)
    {
        const float* hmr = g_hm + (size_t)r * MMn * DH;
        for (int e = wrp; e < EMn; e += 6) {
            int src = me[e], dst = me[EMn + e];
            float wv[3];
#pragma unroll
            for (int h = 0; h < 3; h++) {
                unsigned u = emax_u[dst][h];
                float emx = __uint_as_float((u & 0x80000000u) ? (u & 0x7fffffffu) : ~u);
                wv[h] = __expf(leaky02(as_s[src][h] + ad_s[dst][h]) - emx);
            }
            if (lane == 0) {
                atomicAdd(&den[dst][0], wv[0]);
                atomicAdd(&den[dst][1], wv[1]);
                atomicAdd(&den[dst][2], wv[2]);
            }
            const float* hp = &hmr[src * DH + lane];
            float* op = &g_outs[((size_t)dst * RR + r) * DH + lane];
#pragma unroll
            for (int k = 0; k < 6; k++)
                atomicAdd(op + 32 * k, wv[k >> 1] * __ldg(hp + 32 * k));
        }
    }
    __syncthreads();

    // phase 5: normalize + bias + relu
    {
        int hd = j >> 6;
        float bj = __ldg(&mbias[r * DH + j]);
        for (int m = 0; m < MMn; m++) {
            float dd = den[m][hd];
            float v = __ldcg(&g_outs[((size_t)m * RR + r) * DH + j]);
            v = v / (dd > 0.f ? dd : 1.f) + bj;
            v = fmaxf(v, 0.f);
            g_outs[((size_t)m * RR + r) * DH + j] = v;
            mxs[m][j] = v;
        }
    }
    __syncthreads();

    // phase 6: semantic score
    if (j < SSn) {
        float acc2[MMn];
#pragma unroll
        for (int m = 0; m < MMn; m++) acc2[m] = 0.f;
        for (int d = 0; d < DH; d++) {
            float rw = __ldg(&Wsem[d * SSn + j]);
#pragma unroll
            for (int m = 0; m < MMn; m++) acc2[m] = fmaf(mxs[m][d], rw, acc2[m]);
        }
        float bs = __ldg(&bsem[j]), qs = __ldg(&qsem[j]);
        for (int m = 0; m < MMn; m++)
            atomicAdd(&score_s[m], tanhf(acc2[m] + bs) * qs);
    }
    __syncthreads();
    if (j < MMn) g_score[j * RR + r] = score_s[j];
}

// ---------------- softmax over relations + fusion ------------------------------
__global__ __launch_bounds__(192) void final_kernel(float* __restrict__ out) {
    __shared__ float beta[MMn][RR];
    const int j = threadIdx.x;
    if (j < MMn) {
        float s[RR];
        float mx = -1e30f;
#pragma unroll
        for (int r = 0; r < RR; r++) { s[r] = g_score[j * RR + r]; mx = fmaxf(mx, s[r]); }
        float sum = 0.f;
#pragma unroll
        for (int r = 0; r < RR; r++) { s[r] = __expf(s[r] - mx); sum += s[r]; }
        float inv = 1.f / sum;
#pragma unroll
        for (int r = 0; r < RR; r++) beta[j][r] = s[r] * inv;
    }
    __syncthreads();
    for (int m = 0; m < MMn; m++) {
        float v = 0.f;
#pragma unroll
        for (int r = 0; r < RR; r++)
            v = fmaf(g_outs[((size_t)m * RR + r) * DH + j], beta[m][r], v);
        out[m * DH + j] = v;
    }
}

// ---------------- host launch ---------------------------------------------------
extern "C" void kernel_launch(void* const* d_in, const int* in_sizes, int n_in,
                              void* d_out, int out_size) {
    const float* ppi_x        = (const float*)d_in[0];
    const float* metagraph_x  = (const float*)d_in[1];
    const float* ppi_lin      = (const float*)d_in[2];
    const float* ppi_att_src  = (const float*)d_in[3];
    const float* ppi_att_dst  = (const float*)d_in[4];
    const float* ppi_bias     = (const float*)d_in[5];
    const float* meta_lin     = (const float*)d_in[6];
    const float* meta_att_src = (const float*)d_in[7];
    const float* meta_att_dst = (const float*)d_in[8];
    const float* meta_bias    = (const float*)d_in[9];
    const float* W_sem        = (const float*)d_in[10];
    const float* b_sem        = (const float*)d_in[11];
    const float* q_sem        = (const float*)d_in[12];
    const int*   ppi_edges    = (const int*)d_in[13];
    const int*   meta_edges   = (const int*)d_in[14];
    const int*   tissue_nb    = (const int*)d_in[15];
    float* out = (float*)d_out;

    // order chosen so the profiler's captured launch (4th) is sgemm_kernel
    zeroA_kernel<<<5000, 256>>>();
    zeroB_kernel<<<144, 256>>>();
    diff_mat_kernel<<<1, 256>>>(tissue_nb);
    sgemm_kernel<<<dim3(157, 2, CT), 256>>>(ppi_x, ppi_lin, ppi_att_src, ppi_att_dst);
    passA_kernel<<<dim3(1250, CT), 256>>>(ppi_edges);
    invden_kernel<<<5000, 256>>>();
    passB_kernel<<<dim3(1250, CT), 256>>>(ppi_edges);
    passC_kernel<<<dim3(157, CT), 256>>>();
    diff_apply_kernel<<<1, 192>>>(metagraph_x, ppi_bias);
    meta_kernel<<<RR, 192>>>(meta_lin, meta_att_src, meta_att_dst, meta_bias,
                             meta_edges, W_sem, b_sem, q_sem);
    final_kernel<<<1, 192>>>(out);
}